// round 14
// baseline (speedup 1.0000x reference)
#include <cuda_runtime.h>
#include <cuda_fp16.h>
#include <cstdint>

#define BATCH   32768
#define WIDTH   256
#define NNODES  8
#define NEDGE   28
#define NPART   512

// ---- device scratch -------------------------------------------------------
__device__ __half g_acc[6][(size_t)BATCH * WIDTH];  // unnormalized acc, nodes 1..6
__device__ __half g_x0[(size_t)BATCH * WIDTH];      // x converted to fp16
__device__ __half g_Wt[NEDGE * WIDTH * WIDTH];      // W transposed fp16: Wt[e][n][k]
__device__ float g_part[NNODES][NPART];             // per-node sumsq partials

// ---- PTX helpers ----------------------------------------------------------
__device__ __forceinline__ uint32_t smem_u32(const void* p) {
    uint32_t a;
    asm("{ .reg .u64 t; cvta.to.shared.u64 t, %1; cvt.u32.u64 %0, t; }" : "=r"(a) : "l"(p));
    return a;
}
__device__ __forceinline__ void cp16(uint32_t dst, const void* src) {
    asm volatile("cp.async.cg.shared.global [%0], [%1], 16;" :: "r"(dst), "l"(src) : "memory");
}
__device__ __forceinline__ void cp_commit() {
    asm volatile("cp.async.commit_group;" ::: "memory");
}
template <int N> __device__ __forceinline__ void cp_wait() {
    asm volatile("cp.async.wait_group %0;" :: "n"(N) : "memory");
}
__device__ __forceinline__ void ldsm4(uint32_t* r, uint32_t a) {
    asm volatile("ldmatrix.sync.aligned.m8n8.x4.shared.b16 {%0,%1,%2,%3}, [%4];"
                 : "=r"(r[0]), "=r"(r[1]), "=r"(r[2]), "=r"(r[3]) : "r"(a));
}
// f16-accumulate: d[0] = row g cols {2t,2t+1}, d[1] = row g+8
__device__ __forceinline__ void mma_f16(uint32_t* d, const uint32_t* a, uint32_t b0, uint32_t b1) {
    asm volatile(
        "mma.sync.aligned.m16n8k16.row.col.f16.f16.f16.f16 "
        "{%0,%1}, {%2,%3,%4,%5}, {%6,%7}, {%0,%1};"
        : "+r"(d[0]), "+r"(d[1])
        : "r"(a[0]), "r"(a[1]), "r"(a[2]), "r"(a[3]), "r"(b0), "r"(b1));
}

// ---------------------------------------------------------------------------
// transpose + convert: Wt[e][n][k] = f16(W[e][k][n])
// ---------------------------------------------------------------------------
__global__ __launch_bounds__(256) void transpose_kernel(const float* __restrict__ W) {
    __shared__ float t[32][33];
    int e = blockIdx.z;
    int bx = blockIdx.x * 32, by = blockIdx.y * 32;
    const float* We = W + (size_t)e * WIDTH * WIDTH;
    __half* Wte = g_Wt + (size_t)e * WIDTH * WIDTH;
    int x = threadIdx.x, y = threadIdx.y;  // block (32, 8)
#pragma unroll
    for (int r = 0; r < 32; r += 8) t[y + r][x] = We[(size_t)(by + y + r) * WIDTH + bx + x];
    __syncthreads();
#pragma unroll
    for (int r = 0; r < 32; r += 8)
        Wte[(size_t)(bx + y + r) * WIDTH + by + x] = __float2half(t[x][y + r]);
}

// ---------------------------------------------------------------------------
// sumsq of x + fp16 conversion (512 partials)
// ---------------------------------------------------------------------------
__global__ __launch_bounds__(256) void sumsq_kernel(const float* __restrict__ x) {
    __shared__ float s[256];
    float acc = 0.f;
    const size_t n = (size_t)BATCH * WIDTH;
    for (size_t i = (size_t)blockIdx.x * 256 + threadIdx.x; i < n; i += (size_t)gridDim.x * 256) {
        float v = x[i];
        g_x0[i] = __float2half(v);
        acc += v * v;
    }
    s[threadIdx.x] = acc;
    __syncthreads();
    for (int o = 128; o > 0; o >>= 1) {
        if (threadIdx.x < o) s[threadIdx.x] += s[threadIdx.x + o];
        __syncthreads();
    }
    if (threadIdx.x == 0) g_part[0][blockIdx.x] = s[0];
}

// ===========================================================================
// Layers 1..6: CTA 128x128, 16 warps (4m x 4n), warp tile 32x32, f16 C+S.
// Quarter-K (64) stages, 3-ring (96KB) -> 2 CTAs/SM (forced 64 regs).
// grid (2, 256) = 512 CTAs.
// ===========================================================================
#define BSTG_BYTES 32768          // A 16KB + B 16KB
#define BNSTG      3
#define BSM_RED    (BNSTG * BSTG_BYTES)   // 98304
#define BSM_INV    (BSM_RED + 16 * 4)
#define BSMEM_BYTES (BSM_INV + 8 * 4)

__global__ void __launch_bounds__(512, 2) layer_big(
    int j,
    const float* __restrict__ bias)
{
    extern __shared__ char smem[];
    const uint32_t sb = smem_u32(smem);
    float* s_warp = reinterpret_cast<float*>(smem + BSM_RED);
    float* s_inv = reinterpret_cast<float*>(smem + BSM_INV);
    const int tid = threadIdx.x;
    const int lane = tid & 31;
    const int wid = tid >> 5;
    const int wm = wid & 3;
    const int wn = wid >> 2;
    // alternate sweep direction per layer: layer j+1 reads layer j's freshest
    // (last-written, L2-hot) tiles first
    const int m0 = (j & 1) ? (int)blockIdx.y * 128 : (BATCH - 128 - (int)blockIdx.y * 128);
    const int n0 = blockIdx.x * 128;
    const int base_e = j * (j - 1) / 2;

    if (wid < j) {
        float acc = 0.f;
#pragma unroll
        for (int i = 0; i < NPART / 32; ++i) acc += g_part[wid][i * 32 + lane];
#pragma unroll
        for (int o = 16; o > 0; o >>= 1) acc += __shfl_xor_sync(0xFFFFFFFFu, acc, o);
        if (lane == 0) s_inv[wid] = rsqrtf(acc);
    }

    const int g = lane >> 2;
    const int t = lane & 3;
    const int sel = lane >> 3;
    const int rr = lane & 7;
    const int h = sel >> 1;

    uint32_t aoff[2], boff[2];
#pragma unroll
    for (int mf = 0; mf < 2; ++mf)
        aoff[mf] = (uint32_t)((wm * 32 + mf * 16 + rr + (sel & 1) * 8) * 128);
#pragma unroll
    for (int nf2 = 0; nf2 < 2; ++nf2)
        boff[nf2] = (uint32_t)(16384 + (wn * 32 + nf2 * 16 + rr + (sel & 1) * 8) * 128);

    uint32_t C[2][4][2];
    __half2 S[2][4][2];
    const __half2 h2zero = __floats2half2_rn(0.f, 0.f);
#pragma unroll
    for (int a = 0; a < 2; ++a)
#pragma unroll
        for (int b = 0; b < 4; ++b) { S[a][b][0] = h2zero; S[a][b][1] = h2zero; }

    const int T = j * 4;   // 4 quarter-K stages per edge (K = 256)

    auto load_stage = [&](int tt) {
        if (tt < T) {
            const int e = tt >> 2, kq = tt & 3;
            const char* Asrc = (const char*)((e == 0) ? g_x0 : g_acc[e - 1])
                               + (size_t)m0 * 512 + (size_t)kq * 128;
            const char* Bsrc = (const char*)(g_Wt + (size_t)(base_e + e) * WIDTH * WIDTH)
                               + (size_t)n0 * 512 + (size_t)kq * 128;
            const uint32_t sbase = sb + (uint32_t)(tt % BNSTG) * BSTG_BYTES;
#pragma unroll
            for (int q = 0; q < 4; ++q) {
                int c = q * 512 + tid;             // 0..2047: A first 1024, B 1024
                if (c < 1024) {
                    int r = c >> 3, u = c & 7;
                    uint32_t sw = (uint32_t)(r * 128 + ((u ^ (r & 7)) << 4));
                    cp16(sbase + sw, Asrc + (size_t)r * 512 + u * 16);
                } else {
                    int cb = c - 1024;
                    int r = cb >> 3, u = cb & 7;
                    uint32_t sw = (uint32_t)(r * 128 + ((u ^ (r & 7)) << 4));
                    cp16(sbase + 16384 + sw, Bsrc + (size_t)r * 512 + u * 16);
                }
            }
        }
        cp_commit();
    };

    load_stage(0);
    load_stage(1);

    for (int tt = 0; tt < T; ++tt) {
        cp_wait<1>();
        __syncthreads();
        load_stage(tt + 2);           // slot (tt+2)%3 disjoint from tt, tt+1

        if ((tt & 3) == 0) {
#pragma unroll
            for (int a = 0; a < 2; ++a)
#pragma unroll
                for (int b = 0; b < 4; ++b) { C[a][b][0] = 0u; C[a][b][1] = 0u; }
        }

        const uint32_t sbase = sb + (uint32_t)(tt % BNSTG) * BSTG_BYTES;
#pragma unroll
        for (int ks = 0; ks < 4; ++ks) {          // 4 k16 fragments = 64 k
            const uint32_t gsw = (uint32_t)(((2 * ks + h) ^ rr) << 4);
            uint32_t a[2][4], b[2][4];
#pragma unroll
            for (int mf = 0; mf < 2; ++mf) ldsm4(a[mf], sbase + aoff[mf] + gsw);
#pragma unroll
            for (int nf2 = 0; nf2 < 2; ++nf2) ldsm4(b[nf2], sbase + boff[nf2] + gsw);
#pragma unroll
            for (int mf = 0; mf < 2; ++mf)
#pragma unroll
                for (int nf = 0; nf < 4; ++nf)
                    mma_f16(C[mf][nf], a[mf], b[nf >> 1][nf & 1], b[nf >> 1][2 + (nf & 1)]);
        }

        if ((tt & 3) == 3) {
            const int e = tt >> 2;
            const __half2 inv2 = __float2half2_rn(s_inv[e]);
            const float* brow = bias + (size_t)(base_e + e) * WIDTH + n0 + wn * 32;
#pragma unroll
            for (int nf = 0; nf < 4; ++nf) {
                const __half2 b2 = __floats2half2_rn(__ldg(brow + nf * 8 + 2 * t),
                                                     __ldg(brow + nf * 8 + 2 * t + 1));
#pragma unroll
                for (int mf = 0; mf < 2; ++mf) {
#pragma unroll
                    for (int hh = 0; hh < 2; ++hh) {
                        __half2 c = *reinterpret_cast<__half2*>(&C[mf][nf][hh]);
                        S[mf][nf][hh] = __hadd2(S[mf][nf][hh],
                                                __hmax2(__hfma2(c, inv2, b2), h2zero));
                    }
                }
            }
        }
    }

    // write result tile (half2 stores) + sumsq
    float ss = 0.f;
    __half* dst = &g_acc[j - 1][0];
#pragma unroll
    for (int mf = 0; mf < 2; ++mf)
#pragma unroll
        for (int hh = 0; hh < 2; ++hh) {
            const int row = m0 + wm * 32 + mf * 16 + g + hh * 8;
            __half* dr = dst + (size_t)row * WIDTH + n0 + wn * 32;
#pragma unroll
            for (int nf = 0; nf < 4; ++nf) {
                __half2 v = S[mf][nf][hh];
                *reinterpret_cast<__half2*>(dr + nf * 8 + 2 * t) = v;
                float2 f = __half22float2(v);
                ss += f.x * f.x + f.y * f.y;
            }
        }

#pragma unroll
    for (int o = 16; o > 0; o >>= 1) ss += __shfl_xor_sync(0xFFFFFFFFu, ss, o);
    if (lane == 0) s_warp[wid] = ss;
    __syncthreads();
    if (wid == 0) {
        float v = (lane < 16) ? s_warp[lane] : 0.f;
#pragma unroll
        for (int o = 8; o > 0; o >>= 1) v += __shfl_xor_sync(0xFFFFFFFFu, v, o);
        if (lane == 0) g_part[j][blockIdx.y * 2 + blockIdx.x] = v;
    }
}

// ===========================================================================
// Layer 7: CTA 128x128, warp 32x32, f16 C + fp32 S, fp32 out.
// Half-K (128) stages, 3-ring. grid (2, 256).
// ===========================================================================
#define LSTG_BYTES 65536
#define LNSTG      3
#define LSM_RED    (LNSTG * LSTG_BYTES)
#define LSM_INV    (LSM_RED + 16 * 4)
#define LSMEM_BYTES (LSM_INV + 8 * 4)

__global__ void __launch_bounds__(512, 1) layer_last(
    const float* __restrict__ bias,
    float* __restrict__ out)
{
    extern __shared__ char smem[];
    const uint32_t sb = smem_u32(smem);
    float* s_warp = reinterpret_cast<float*>(smem + LSM_RED);
    float* s_inv = reinterpret_cast<float*>(smem + LSM_INV);
    const int tid = threadIdx.x;
    const int lane = tid & 31;
    const int wid = tid >> 5;
    const int wm = wid & 3;
    const int wn = wid >> 2;
    const int m0 = blockIdx.y * 128;   // j=7 odd -> ascending (layer 6 wrote descending)
    const int n0 = blockIdx.x * 128;
    const int j = 7, base_e = 21;

    if (wid < j) {
        float acc = 0.f;
#pragma unroll
        for (int i = 0; i < NPART / 32; ++i) acc += g_part[wid][i * 32 + lane];
#pragma unroll
        for (int o = 16; o > 0; o >>= 1) acc += __shfl_xor_sync(0xFFFFFFFFu, acc, o);
        if (lane == 0) s_inv[wid] = rsqrtf(acc);
    }

    const int g = lane >> 2;
    const int t = lane & 3;
    const int sel = lane >> 3;
    const int rr = lane & 7;
    const int h = sel >> 1;

    uint32_t aoff[2], boff[2];
#pragma unroll
    for (int mf = 0; mf < 2; ++mf)
        aoff[mf] = (uint32_t)((wm * 32 + mf * 16 + rr + (sel & 1) * 8) * 128);
#pragma unroll
    for (int nf2 = 0; nf2 < 2; ++nf2)
        boff[nf2] = (uint32_t)((wn * 32 + nf2 * 16 + rr + (sel & 1) * 8) * 128);

    uint32_t C[2][4][2];
    float S[2][4][4];
#pragma unroll
    for (int a = 0; a < 2; ++a)
#pragma unroll
        for (int b = 0; b < 4; ++b)
#pragma unroll
            for (int c = 0; c < 4; ++c) S[a][b][c] = 0.f;

    const int T = j * 2;

    auto load_stage = [&](int tt) {
        if (tt < T) {
            const int e = tt >> 1, kh = tt & 1;
            const char* Asrc = (const char*)((e == 0) ? g_x0 : g_acc[e - 1])
                               + (size_t)m0 * 512 + (size_t)kh * 256;
            const char* Bsrc = (const char*)(g_Wt + (size_t)(base_e + e) * WIDTH * WIDTH)
                               + (size_t)n0 * 512 + (size_t)kh * 256;
            const uint32_t sbase = sb + (uint32_t)(tt % LNSTG) * LSTG_BYTES;
#pragma unroll
            for (int q = 0; q < 4; ++q) {
                int c = q * 512 + tid;
                int kb = c >> 10;
                int r = (c & 1023) >> 3;
                int u = c & 7;
                uint32_t sw = (uint32_t)(r * 128 + ((u ^ (r & 7)) << 4));
                uint32_t dkb = (uint32_t)kb * 16384;
                const size_t goff = (size_t)r * 512 + kb * 128 + u * 16;
                cp16(sbase + dkb + sw, Asrc + goff);
                cp16(sbase + 32768 + dkb + sw, Bsrc + goff);
            }
        }
        cp_commit();
    };

    load_stage(0);
    load_stage(1);

    for (int tt = 0; tt < T; ++tt) {
        cp_wait<1>();
        __syncthreads();
        load_stage(tt + 2);

        if ((tt & 1) == 0) {
#pragma unroll
            for (int a = 0; a < 2; ++a)
#pragma unroll
                for (int b = 0; b < 4; ++b) { C[a][b][0] = 0u; C[a][b][1] = 0u; }
        }

        const uint32_t sbase = sb + (uint32_t)(tt % LNSTG) * LSTG_BYTES;
#pragma unroll
        for (int ks = 0; ks < 8; ++ks) {
            const uint32_t kbo = (uint32_t)(ks >> 2) * 16384;
            const int ks2 = ks & 3;
            const uint32_t gsw = (uint32_t)(((2 * ks2 + h) ^ rr) << 4);
            uint32_t a[2][4], b[2][4];
#pragma unroll
            for (int mf = 0; mf < 2; ++mf) ldsm4(a[mf], sbase + kbo + aoff[mf] + gsw);
#pragma unroll
            for (int nf2 = 0; nf2 < 2; ++nf2)
                ldsm4(b[nf2], sbase + 32768 + kbo + boff[nf2] + gsw);
#pragma unroll
            for (int mf = 0; mf < 2; ++mf)
#pragma unroll
                for (int nf = 0; nf < 4; ++nf)
                    mma_f16(C[mf][nf], a[mf], b[nf >> 1][nf & 1], b[nf >> 1][2 + (nf & 1)]);
        }

        if ((tt & 1) == 1) {
            const int e = tt >> 1;
            const float inv = s_inv[e];
            const float* brow = bias + (size_t)(base_e + e) * WIDTH + n0 + wn * 32;
#pragma unroll
            for (int nf = 0; nf < 4; ++nf) {
                const float b0 = __ldg(brow + nf * 8 + 2 * t);
                const float b1 = __ldg(brow + nf * 8 + 2 * t + 1);
#pragma unroll
                for (int mf = 0; mf < 2; ++mf) {
                    float2 lo = __half22float2(*reinterpret_cast<__half2*>(&C[mf][nf][0]));
                    float2 hi = __half22float2(*reinterpret_cast<__half2*>(&C[mf][nf][1]));
                    S[mf][nf][0] += fmaxf(fmaf(lo.x, inv, b0), 0.f);
                    S[mf][nf][1] += fmaxf(fmaf(lo.y, inv, b1), 0.f);
                    S[mf][nf][2] += fmaxf(fmaf(hi.x, inv, b0), 0.f);
                    S[mf][nf][3] += fmaxf(fmaf(hi.y, inv, b1), 0.f);
                }
            }
        }
    }

    float ss = 0.f;
#pragma unroll
    for (int mf = 0; mf < 2; ++mf)
#pragma unroll
        for (int half = 0; half < 2; ++half) {
            const int row = m0 + wm * 32 + mf * 16 + g + half * 8;
            float* dr = out + (size_t)row * WIDTH + n0 + wn * 32;
#pragma unroll
            for (int nf = 0; nf < 4; ++nf) {
                float v0 = S[mf][nf][half * 2];
                float v1 = S[mf][nf][half * 2 + 1];
                *reinterpret_cast<float2*>(dr + nf * 8 + 2 * t) = make_float2(v0, v1);
                ss += v0 * v0 + v1 * v1;
            }
        }

#pragma unroll
    for (int o = 16; o > 0; o >>= 1) ss += __shfl_xor_sync(0xFFFFFFFFu, ss, o);
    if (lane == 0) s_warp[wid] = ss;
    __syncthreads();
    if (wid == 0) {
        float v = (lane < 16) ? s_warp[lane] : 0.f;
#pragma unroll
        for (int o = 8; o > 0; o >>= 1) v += __shfl_xor_sync(0xFFFFFFFFu, v, o);
        if (lane == 0) g_part[7][blockIdx.y * 2 + blockIdx.x] = v;
    }
}

// ---------------------------------------------------------------------------
// Final: out *= 1/||acc_7|| (double-l2norm collapses). 512 partials.
// ---------------------------------------------------------------------------
__global__ __launch_bounds__(256) void scale_kernel(float* __restrict__ out) {
    __shared__ float s[256];
    s[threadIdx.x] = g_part[7][threadIdx.x] + g_part[7][threadIdx.x + 256];
    __syncthreads();
    for (int o = 128; o > 0; o >>= 1) {
        if (threadIdx.x < o) s[threadIdx.x] += s[threadIdx.x + o];
        __syncthreads();
    }
    const float inv = rsqrtf(s[0]);
    const size_t n = (size_t)BATCH * WIDTH;
    for (size_t i = (size_t)blockIdx.x * 256 + threadIdx.x; i < n; i += (size_t)gridDim.x * 256)
        out[i] *= inv;
}

// ---------------------------------------------------------------------------
extern "C" void kernel_launch(void* const* d_in, const int* in_sizes, int n_in,
                              void* d_out, int out_size)
{
    const float* x = nullptr;
    const float* W = nullptr;
    const float* b = nullptr;
    for (int i = 0; i < n_in; ++i) {
        if (in_sizes[i] == BATCH * WIDTH)                 x = (const float*)d_in[i];
        else if (in_sizes[i] == NEDGE * WIDTH * WIDTH)    W = (const float*)d_in[i];
        else if (in_sizes[i] == NEDGE * WIDTH)            b = (const float*)d_in[i];
    }
    float* out = (float*)d_out;

    static bool attr_set = false;
    if (!attr_set) {
        cudaFuncSetAttribute(layer_big, cudaFuncAttributeMaxDynamicSharedMemorySize, BSMEM_BYTES);
        cudaFuncSetAttribute(layer_last, cudaFuncAttributeMaxDynamicSharedMemorySize, LSMEM_BYTES);
        attr_set = true;
    }

    transpose_kernel<<<dim3(8, 8, NEDGE), dim3(32, 8)>>>(W);
    sumsq_kernel<<<NPART, 256>>>(x);

    dim3 grid(2, BATCH / 128);   // (2, 256) = 512 CTAs
    for (int j = 1; j <= 6; ++j)
        layer_big<<<grid, 512, BSMEM_BYTES>>>(j, b);

    layer_last<<<grid, 512, LSMEM_BYTES>>>(b, out);

    scale_kernel<<<2048, 256>>>(out);
}

// round 17
// speedup vs baseline: 1.0779x; 1.0779x over previous
#include <cuda_runtime.h>
#include <cuda_fp16.h>
#include <cstdint>

#define BATCH   32768
#define WIDTH   256
#define NNODES  8
#define NEDGE   28
#define NPART   512

// ---- device scratch -------------------------------------------------------
__device__ __half g_acc[6][(size_t)BATCH * WIDTH];  // unnormalized acc, nodes 1..6
__device__ __half g_x0[(size_t)BATCH * WIDTH];      // x converted to fp16
__device__ __half g_Wt[NEDGE * WIDTH * WIDTH];      // W transposed fp16: Wt[e][n][k]
__device__ float g_part[NNODES][NPART];             // per-node sumsq partials

// ---- PTX helpers ----------------------------------------------------------
__device__ __forceinline__ uint32_t smem_u32(const void* p) {
    uint32_t a;
    asm("{ .reg .u64 t; cvta.to.shared.u64 t, %1; cvt.u32.u64 %0, t; }" : "=r"(a) : "l"(p));
    return a;
}
__device__ __forceinline__ void cp16(uint32_t dst, const void* src) {
    asm volatile("cp.async.cg.shared.global [%0], [%1], 16;" :: "r"(dst), "l"(src) : "memory");
}
__device__ __forceinline__ void cp_commit() {
    asm volatile("cp.async.commit_group;" ::: "memory");
}
template <int N> __device__ __forceinline__ void cp_wait() {
    asm volatile("cp.async.wait_group %0;" :: "n"(N) : "memory");
}
__device__ __forceinline__ void ldsm4(uint32_t* r, uint32_t a) {
    asm volatile("ldmatrix.sync.aligned.m8n8.x4.shared.b16 {%0,%1,%2,%3}, [%4];"
                 : "=r"(r[0]), "=r"(r[1]), "=r"(r[2]), "=r"(r[3]) : "r"(a));
}
// f16-accumulate: d[0] = row g cols {2t,2t+1}, d[1] = row g+8
__device__ __forceinline__ void mma_f16(uint32_t* d, const uint32_t* a, uint32_t b0, uint32_t b1) {
    asm volatile(
        "mma.sync.aligned.m16n8k16.row.col.f16.f16.f16.f16 "
        "{%0,%1}, {%2,%3,%4,%5}, {%6,%7}, {%0,%1};"
        : "+r"(d[0]), "+r"(d[1])
        : "r"(a[0]), "r"(a[1]), "r"(a[2]), "r"(a[3]), "r"(b0), "r"(b1));
}

// ---------------------------------------------------------------------------
// transpose + convert: Wt[e][n][k] = f16(W[e][k][n])
// ---------------------------------------------------------------------------
__global__ __launch_bounds__(256) void transpose_kernel(const float* __restrict__ W) {
    __shared__ float t[32][33];
    int e = blockIdx.z;
    int bx = blockIdx.x * 32, by = blockIdx.y * 32;
    const float* We = W + (size_t)e * WIDTH * WIDTH;
    __half* Wte = g_Wt + (size_t)e * WIDTH * WIDTH;
    int x = threadIdx.x, y = threadIdx.y;  // block (32, 8)
#pragma unroll
    for (int r = 0; r < 32; r += 8) t[y + r][x] = We[(size_t)(by + y + r) * WIDTH + bx + x];
    __syncthreads();
#pragma unroll
    for (int r = 0; r < 32; r += 8)
        Wte[(size_t)(bx + y + r) * WIDTH + by + x] = __float2half(t[x][y + r]);
}

// ---------------------------------------------------------------------------
// sumsq of x + fp16 conversion (512 partials)
// ---------------------------------------------------------------------------
__global__ __launch_bounds__(256) void sumsq_kernel(const float* __restrict__ x) {
    __shared__ float s[256];
    float acc = 0.f;
    const size_t n = (size_t)BATCH * WIDTH;
    for (size_t i = (size_t)blockIdx.x * 256 + threadIdx.x; i < n; i += (size_t)gridDim.x * 256) {
        float v = x[i];
        g_x0[i] = __float2half(v);
        acc += v * v;
    }
    s[threadIdx.x] = acc;
    __syncthreads();
    for (int o = 128; o > 0; o >>= 1) {
        if (threadIdx.x < o) s[threadIdx.x] += s[threadIdx.x + o];
        __syncthreads();
    }
    if (threadIdx.x == 0) g_part[0][blockIdx.x] = s[0];
}

// ===========================================================================
// Layers 1..6: CTA 128x128, 8 warps (2m x 4n), warp tile 64x32, f16 C+S.
// Quarter-K (64) stages, 3-ring (96KB). 256 threads, 2 CTAs/SM.
// grid (2, 256) = 512 CTAs.
// ===========================================================================
#define BSTG_BYTES 32768          // A 16KB + B 16KB
#define BNSTG      3
#define BSM_RED    (BNSTG * BSTG_BYTES)   // 98304
#define BSM_INV    (BSM_RED + 8 * 4)
#define BSMEM_BYTES (BSM_INV + 8 * 4)

__global__ void __launch_bounds__(256, 2) layer_big(
    int j,
    const float* __restrict__ bias)
{
    extern __shared__ char smem[];
    const uint32_t sb = smem_u32(smem);
    float* s_warp = reinterpret_cast<float*>(smem + BSM_RED);
    float* s_inv = reinterpret_cast<float*>(smem + BSM_INV);
    const int tid = threadIdx.x;
    const int lane = tid & 31;
    const int wid = tid >> 5;        // 0..7
    const int wm = wid & 1;          // 0..1, 64 rows each
    const int wn = wid >> 1;         // 0..3, 32 cols each
    // alternate sweep direction per layer (reads predecessor's freshest tiles first)
    const int m0 = (j & 1) ? (int)blockIdx.y * 128 : (BATCH - 128 - (int)blockIdx.y * 128);
    const int n0 = blockIdx.x * 128;
    const int base_e = j * (j - 1) / 2;

    if (wid < j) {
        float acc = 0.f;
#pragma unroll
        for (int i = 0; i < NPART / 32; ++i) acc += g_part[wid][i * 32 + lane];
#pragma unroll
        for (int o = 16; o > 0; o >>= 1) acc += __shfl_xor_sync(0xFFFFFFFFu, acc, o);
        if (lane == 0) s_inv[wid] = rsqrtf(acc);
    }

    const int g = lane >> 2;
    const int t = lane & 3;
    const int sel = lane >> 3;
    const int rr = lane & 7;
    const int h = sel >> 1;

    uint32_t aoff[4], boff[2];
#pragma unroll
    for (int mf = 0; mf < 4; ++mf)
        aoff[mf] = (uint32_t)((wm * 64 + mf * 16 + rr + (sel & 1) * 8) * 128);
#pragma unroll
    for (int nf2 = 0; nf2 < 2; ++nf2)
        boff[nf2] = (uint32_t)(16384 + (wn * 32 + nf2 * 16 + rr + (sel & 1) * 8) * 128);

    uint32_t C[4][4][2];
    __half2 S[4][4][2];
    const __half2 h2zero = __floats2half2_rn(0.f, 0.f);
#pragma unroll
    for (int a = 0; a < 4; ++a)
#pragma unroll
        for (int b = 0; b < 4; ++b) { S[a][b][0] = h2zero; S[a][b][1] = h2zero; }

    const int T = j * 4;   // 4 quarter-K stages per edge (K = 256)

    auto load_stage = [&](int tt) {
        if (tt < T) {
            const int e = tt >> 2, kq = tt & 3;
            const char* Asrc = (const char*)((e == 0) ? g_x0 : g_acc[e - 1])
                               + (size_t)m0 * 512 + (size_t)kq * 128;
            const char* Bsrc = (const char*)(g_Wt + (size_t)(base_e + e) * WIDTH * WIDTH)
                               + (size_t)n0 * 512 + (size_t)kq * 128;
            const uint32_t sbase = sb + (uint32_t)(tt % BNSTG) * BSTG_BYTES;
#pragma unroll
            for (int q = 0; q < 8; ++q) {
                int c = q * 256 + tid;             // 0..2047: A first 1024, B 1024
                if (c < 1024) {
                    int r = c >> 3, u = c & 7;
                    uint32_t sw = (uint32_t)(r * 128 + ((u ^ (r & 7)) << 4));
                    cp16(sbase + sw, Asrc + (size_t)r * 512 + u * 16);
                } else {
                    int cb = c - 1024;
                    int r = cb >> 3, u = cb & 7;
                    uint32_t sw = (uint32_t)(r * 128 + ((u ^ (r & 7)) << 4));
                    cp16(sbase + 16384 + sw, Bsrc + (size_t)r * 512 + u * 16);
                }
            }
        }
        cp_commit();
    };

    load_stage(0);
    load_stage(1);

    for (int tt = 0; tt < T; ++tt) {
        cp_wait<1>();
        __syncthreads();
        load_stage(tt + 2);           // slot (tt+2)%3 disjoint from tt, tt+1

        if ((tt & 3) == 0) {
#pragma unroll
            for (int a = 0; a < 4; ++a)
#pragma unroll
                for (int b = 0; b < 4; ++b) { C[a][b][0] = 0u; C[a][b][1] = 0u; }
        }

        const uint32_t sbase = sb + (uint32_t)(tt % BNSTG) * BSTG_BYTES;
#pragma unroll
        for (int ks = 0; ks < 4; ++ks) {          // 4 k16 fragments = 64 k
            const uint32_t gsw = (uint32_t)(((2 * ks + h) ^ rr) << 4);
            uint32_t a[4][4], b[2][4];
#pragma unroll
            for (int mf = 0; mf < 4; ++mf) ldsm4(a[mf], sbase + aoff[mf] + gsw);
#pragma unroll
            for (int nf2 = 0; nf2 < 2; ++nf2) ldsm4(b[nf2], sbase + boff[nf2] + gsw);
#pragma unroll
            for (int mf = 0; mf < 4; ++mf)
#pragma unroll
                for (int nf = 0; nf < 4; ++nf)
                    mma_f16(C[mf][nf], a[mf], b[nf >> 1][nf & 1], b[nf >> 1][2 + (nf & 1)]);
        }

        if ((tt & 3) == 3) {
            const int e = tt >> 2;
            const __half2 inv2 = __float2half2_rn(s_inv[e]);
            const float* brow = bias + (size_t)(base_e + e) * WIDTH + n0 + wn * 32;
#pragma unroll
            for (int nf = 0; nf < 4; ++nf) {
                const __half2 b2 = __floats2half2_rn(__ldg(brow + nf * 8 + 2 * t),
                                                     __ldg(brow + nf * 8 + 2 * t + 1));
#pragma unroll
                for (int mf = 0; mf < 4; ++mf) {
#pragma unroll
                    for (int hh = 0; hh < 2; ++hh) {
                        __half2 c = *reinterpret_cast<__half2*>(&C[mf][nf][hh]);
                        S[mf][nf][hh] = __hadd2(S[mf][nf][hh],
                                                __hmax2(__hfma2(c, inv2, b2), h2zero));
                    }
                }
            }
        }
    }

    // write result tile (half2 stores) + sumsq
    float ss = 0.f;
    __half* dst = &g_acc[j - 1][0];
#pragma unroll
    for (int mf = 0; mf < 4; ++mf)
#pragma unroll
        for (int hh = 0; hh < 2; ++hh) {
            const int row = m0 + wm * 64 + mf * 16 + g + hh * 8;
            __half* dr = dst + (size_t)row * WIDTH + n0 + wn * 32;
#pragma unroll
            for (int nf = 0; nf < 4; ++nf) {
                __half2 v = S[mf][nf][hh];
                *reinterpret_cast<__half2*>(dr + nf * 8 + 2 * t) = v;
                float2 f = __half22float2(v);
                ss += f.x * f.x + f.y * f.y;
            }
        }

#pragma unroll
    for (int o = 16; o > 0; o >>= 1) ss += __shfl_xor_sync(0xFFFFFFFFu, ss, o);
    if (lane == 0) s_warp[wid] = ss;
    __syncthreads();
    if (wid == 0) {
        float v = (lane < 8) ? s_warp[lane] : 0.f;
#pragma unroll
        for (int o = 4; o > 0; o >>= 1) v += __shfl_xor_sync(0xFFFFFFFFu, v, o);
        if (lane == 0) g_part[j][blockIdx.y * 2 + blockIdx.x] = v;
    }
}

// ===========================================================================
// Layer 7: CTA 128x128, 16 warps, warp 32x32, f16 C + fp32 S, fp32 out.
// Half-K (128) stages, 3-ring. grid (2, 256). (R14-proven.)
// ===========================================================================
#define LSTG_BYTES 65536
#define LNSTG      3
#define LSM_RED    (LNSTG * LSTG_BYTES)
#define LSM_INV    (LSM_RED + 16 * 4)
#define LSMEM_BYTES (LSM_INV + 8 * 4)

__global__ void __launch_bounds__(512, 1) layer_last(
    const float* __restrict__ bias,
    float* __restrict__ out)
{
    extern __shared__ char smem[];
    const uint32_t sb = smem_u32(smem);
    float* s_warp = reinterpret_cast<float*>(smem + LSM_RED);
    float* s_inv = reinterpret_cast<float*>(smem + LSM_INV);
    const int tid = threadIdx.x;
    const int lane = tid & 31;
    const int wid = tid >> 5;
    const int wm = wid & 3;
    const int wn = wid >> 2;
    const int m0 = blockIdx.y * 128;   // j=7 odd -> ascending (layer 6 wrote descending)
    const int n0 = blockIdx.x * 128;
    const int j = 7, base_e = 21;

    if (wid < j) {
        float acc = 0.f;
#pragma unroll
        for (int i = 0; i < NPART / 32; ++i) acc += g_part[wid][i * 32 + lane];
#pragma unroll
        for (int o = 16; o > 0; o >>= 1) acc += __shfl_xor_sync(0xFFFFFFFFu, acc, o);
        if (lane == 0) s_inv[wid] = rsqrtf(acc);
    }

    const int g = lane >> 2;
    const int t = lane & 3;
    const int sel = lane >> 3;
    const int rr = lane & 7;
    const int h = sel >> 1;

    uint32_t aoff[2], boff[2];
#pragma unroll
    for (int mf = 0; mf < 2; ++mf)
        aoff[mf] = (uint32_t)((wm * 32 + mf * 16 + rr + (sel & 1) * 8) * 128);
#pragma unroll
    for (int nf2 = 0; nf2 < 2; ++nf2)
        boff[nf2] = (uint32_t)((wn * 32 + nf2 * 16 + rr + (sel & 1) * 8) * 128);

    uint32_t C[2][4][2];
    float S[2][4][4];
#pragma unroll
    for (int a = 0; a < 2; ++a)
#pragma unroll
        for (int b = 0; b < 4; ++b)
#pragma unroll
            for (int c = 0; c < 4; ++c) S[a][b][c] = 0.f;

    const int T = j * 2;

    auto load_stage = [&](int tt) {
        if (tt < T) {
            const int e = tt >> 1, kh = tt & 1;
            const char* Asrc = (const char*)((e == 0) ? g_x0 : g_acc[e - 1])
                               + (size_t)m0 * 512 + (size_t)kh * 256;
            const char* Bsrc = (const char*)(g_Wt + (size_t)(base_e + e) * WIDTH * WIDTH)
                               + (size_t)n0 * 512 + (size_t)kh * 256;
            const uint32_t sbase = sb + (uint32_t)(tt % LNSTG) * LSTG_BYTES;
#pragma unroll
            for (int q = 0; q < 4; ++q) {
                int c = q * 512 + tid;
                int kb = c >> 10;
                int r = (c & 1023) >> 3;
                int u = c & 7;
                uint32_t sw = (uint32_t)(r * 128 + ((u ^ (r & 7)) << 4));
                uint32_t dkb = (uint32_t)kb * 16384;
                const size_t goff = (size_t)r * 512 + kb * 128 + u * 16;
                cp16(sbase + dkb + sw, Asrc + goff);
                cp16(sbase + 32768 + dkb + sw, Bsrc + goff);
            }
        }
        cp_commit();
    };

    load_stage(0);
    load_stage(1);

    for (int tt = 0; tt < T; ++tt) {
        cp_wait<1>();
        __syncthreads();
        load_stage(tt + 2);

        if ((tt & 1) == 0) {
#pragma unroll
            for (int a = 0; a < 2; ++a)
#pragma unroll
                for (int b = 0; b < 4; ++b) { C[a][b][0] = 0u; C[a][b][1] = 0u; }
        }

        const uint32_t sbase = sb + (uint32_t)(tt % LNSTG) * LSTG_BYTES;
#pragma unroll
        for (int ks = 0; ks < 8; ++ks) {
            const uint32_t kbo = (uint32_t)(ks >> 2) * 16384;
            const int ks2 = ks & 3;
            const uint32_t gsw = (uint32_t)(((2 * ks2 + h) ^ rr) << 4);
            uint32_t a[2][4], b[2][4];
#pragma unroll
            for (int mf = 0; mf < 2; ++mf) ldsm4(a[mf], sbase + kbo + aoff[mf] + gsw);
#pragma unroll
            for (int nf2 = 0; nf2 < 2; ++nf2)
                ldsm4(b[nf2], sbase + 32768 + kbo + boff[nf2] + gsw);
#pragma unroll
            for (int mf = 0; mf < 2; ++mf)
#pragma unroll
                for (int nf = 0; nf < 4; ++nf)
                    mma_f16(C[mf][nf], a[mf], b[nf >> 1][nf & 1], b[nf >> 1][2 + (nf & 1)]);
        }

        if ((tt & 1) == 1) {
            const int e = tt >> 1;
            const float inv = s_inv[e];
            const float* brow = bias + (size_t)(base_e + e) * WIDTH + n0 + wn * 32;
#pragma unroll
            for (int nf = 0; nf < 4; ++nf) {
                const float b0 = __ldg(brow + nf * 8 + 2 * t);
                const float b1 = __ldg(brow + nf * 8 + 2 * t + 1);
#pragma unroll
                for (int mf = 0; mf < 2; ++mf) {
                    float2 lo = __half22float2(*reinterpret_cast<__half2*>(&C[mf][nf][0]));
                    float2 hi = __half22float2(*reinterpret_cast<__half2*>(&C[mf][nf][1]));
                    S[mf][nf][0] += fmaxf(fmaf(lo.x, inv, b0), 0.f);
                    S[mf][nf][1] += fmaxf(fmaf(lo.y, inv, b1), 0.f);
                    S[mf][nf][2] += fmaxf(fmaf(hi.x, inv, b0), 0.f);
                    S[mf][nf][3] += fmaxf(fmaf(hi.y, inv, b1), 0.f);
                }
            }
        }
    }

    float ss = 0.f;
#pragma unroll
    for (int mf = 0; mf < 2; ++mf)
#pragma unroll
        for (int half = 0; half < 2; ++half) {
            const int row = m0 + wm * 32 + mf * 16 + g + half * 8;
            float* dr = out + (size_t)row * WIDTH + n0 + wn * 32;
#pragma unroll
            for (int nf = 0; nf < 4; ++nf) {
                float v0 = S[mf][nf][half * 2];
                float v1 = S[mf][nf][half * 2 + 1];
                *reinterpret_cast<float2*>(dr + nf * 8 + 2 * t) = make_float2(v0, v1);
                ss += v0 * v0 + v1 * v1;
            }
        }

#pragma unroll
    for (int o = 16; o > 0; o >>= 1) ss += __shfl_xor_sync(0xFFFFFFFFu, ss, o);
    if (lane == 0) s_warp[wid] = ss;
    __syncthreads();
    if (wid == 0) {
        float v = (lane < 16) ? s_warp[lane] : 0.f;
#pragma unroll
        for (int o = 8; o > 0; o >>= 1) v += __shfl_xor_sync(0xFFFFFFFFu, v, o);
        if (lane == 0) g_part[7][blockIdx.y * 2 + blockIdx.x] = v;
    }
}

// ---------------------------------------------------------------------------
// Final: out *= 1/||acc_7|| (double-l2norm collapses). 512 partials.
// ---------------------------------------------------------------------------
__global__ __launch_bounds__(256) void scale_kernel(float* __restrict__ out) {
    __shared__ float s[256];
    s[threadIdx.x] = g_part[7][threadIdx.x] + g_part[7][threadIdx.x + 256];
    __syncthreads();
    for (int o = 128; o > 0; o >>= 1) {
        if (threadIdx.x < o) s[threadIdx.x] += s[threadIdx.x + o];
        __syncthreads();
    }
    const float inv = rsqrtf(s[0]);
    const size_t n = (size_t)BATCH * WIDTH;
    for (size_t i = (size_t)blockIdx.x * 256 + threadIdx.x; i < n; i += (size_t)gridDim.x * 256)
        out[i] *= inv;
}

// ---------------------------------------------------------------------------
extern "C" void kernel_launch(void* const* d_in, const int* in_sizes, int n_in,
                              void* d_out, int out_size)
{
    const float* x = nullptr;
    const float* W = nullptr;
    const float* b = nullptr;
    for (int i = 0; i < n_in; ++i) {
        if (in_sizes[i] == BATCH * WIDTH)                 x = (const float*)d_in[i];
        else if (in_sizes[i] == NEDGE * WIDTH * WIDTH)    W = (const float*)d_in[i];
        else if (in_sizes[i] == NEDGE * WIDTH)            b = (const float*)d_in[i];
    }
    float* out = (float*)d_out;

    static bool attr_set = false;
    if (!attr_set) {
        cudaFuncSetAttribute(layer_big, cudaFuncAttributeMaxDynamicSharedMemorySize, BSMEM_BYTES);
        cudaFuncSetAttribute(layer_last, cudaFuncAttributeMaxDynamicSharedMemorySize, LSMEM_BYTES);
        attr_set = true;
    }

    transpose_kernel<<<dim3(8, 8, NEDGE), dim3(32, 8)>>>(W);
    sumsq_kernel<<<NPART, 256>>>(x);

    dim3 grid(2, BATCH / 128);   // (2, 256) = 512 CTAs
    for (int j = 1; j <= 6; ++j)
        layer_big<<<grid, 256, BSMEM_BYTES>>>(j, b);

    layer_last<<<grid, 512, LSMEM_BYTES>>>(b, out);

    scale_kernel<<<2048, 256>>>(out);
}